// round 7
// baseline (speedup 1.0000x reference)
#include <cuda_runtime.h>
#include <math.h>

typedef unsigned long long u64;

// padded phys layout: one 8B slot per 16 amps -> conflict-free in all 3 rounds
__device__ __forceinline__ int PHYS(int i) { return i + (i >> 4); }

__device__ __forceinline__ float2 cmul(float2 a, float2 b) {
    return make_float2(a.x * b.x - a.y * b.y, a.x * b.y + a.y * b.x);
}
__device__ __forceinline__ u64 pack2(float x, float y) {
    u64 r; asm("mov.b64 %0, {%1, %2};" : "=l"(r) : "f"(x), "f"(y)); return r;
}
__device__ __forceinline__ float2 unpack2(u64 v) {
    float2 r; asm("mov.b64 {%0, %1}, %2;" : "=f"(r.x), "=f"(r.y) : "l"(v)); return r;
}
__device__ __forceinline__ u64 swp(u64 v) {
    float2 t = unpack2(v); return pack2(t.y, t.x);
}
__device__ __forceinline__ u64 ffma2(u64 a, u64 b, u64 c) {
    u64 d; asm("fma.rn.f32x2 %0, %1, %2, %3;" : "=l"(d) : "l"(a), "l"(b), "l"(c)); return d;
}
__device__ __forceinline__ u64 fmul2(u64 a, u64 b) {
    u64 d; asm("mul.rn.f32x2 %0, %1, %2;" : "=l"(d) : "l"(a), "l"(b)); return d;
}

// Apply two 4x4 complex stages to 16 register amps.
// Stage A groups quads {A[4c+j]} (low bit-pair); stage B groups {A[4j+c]}.
__device__ __forceinline__ void stage_pair(const float4* __restrict__ MshA,
                                           const float4* __restrict__ MshB,
                                           u64* A) {
    {   // stage A
        u64 mr[16], mi[16];
        #pragma unroll
        for (int e = 0; e < 16; e++) {
            float4 q = MshA[e];
            mr[e] = pack2(q.x, q.y);
            mi[e] = pack2(q.z, q.w);
        }
        #pragma unroll
        for (int c = 0; c < 4; c++) {
            u64 x0 = A[4*c], x1 = A[4*c+1], x2 = A[4*c+2], x3 = A[4*c+3];
            u64 s0 = swp(x0), s1 = swp(x1), s2 = swp(x2), s3 = swp(x3);
            #pragma unroll
            for (int e = 0; e < 4; e++) {
                u64 o = fmul2(mr[e*4+0], x0);
                o = ffma2(mi[e*4+0], s0, o);
                o = ffma2(mr[e*4+1], x1, o); o = ffma2(mi[e*4+1], s1, o);
                o = ffma2(mr[e*4+2], x2, o); o = ffma2(mi[e*4+2], s2, o);
                o = ffma2(mr[e*4+3], x3, o); o = ffma2(mi[e*4+3], s3, o);
                A[4*c+e] = o;
            }
        }
    }
    {   // stage B
        u64 mr[16], mi[16];
        #pragma unroll
        for (int e = 0; e < 16; e++) {
            float4 q = MshB[e];
            mr[e] = pack2(q.x, q.y);
            mi[e] = pack2(q.z, q.w);
        }
        #pragma unroll
        for (int c = 0; c < 4; c++) {
            u64 x0 = A[c], x1 = A[4+c], x2 = A[8+c], x3 = A[12+c];
            u64 s0 = swp(x0), s1 = swp(x1), s2 = swp(x2), s3 = swp(x3);
            #pragma unroll
            for (int e = 0; e < 4; e++) {
                u64 o = fmul2(mr[e*4+0], x0);
                o = ffma2(mi[e*4+0], s0, o);
                o = ffma2(mr[e*4+1], x1, o); o = ffma2(mi[e*4+1], s1, o);
                o = ffma2(mr[e*4+2], x2, o); o = ffma2(mi[e*4+2], s2, o);
                o = ffma2(mr[e*4+3], x3, o); o = ffma2(mi[e*4+3], s3, o);
                A[4*e+c] = o;
            }
        }
    }
}

// Fused: every block (one per SM) redundantly runs the 12-qubit sim + MLP in
// its own smem, then broadcasts its grid-strided slice of the 64 MiB output.
__global__ __launch_bounds__(256, 1)
void qae_fused_kernel(const float* __restrict__ w,     // (3,12,3)
                      const float* __restrict__ W1,    // (32,12)
                      const float* __restrict__ b1,    // (32,)
                      const float* __restrict__ W2,    // (16,32)
                      const float* __restrict__ b2,    // (16,)
                      float4* __restrict__ out, int n4)
{
    __shared__ u64    buf[4352];          // 4096 amps padded (34 KB)
    __shared__ float4 sM4[12][16];        // packed {mx,mx,-my,my} stage mats
    __shared__ float2 sG[36][4];          // per (layer,qubit) fused gate
    __shared__ float2 sHi[64], sLo[64];   // layer-1 product prefix tables
    __shared__ int    sBinv[12];          // basis of inverse CNOT-ring perm
    __shared__ int    smask[12];          // forward-perm parity masks
    __shared__ float  sPart[8][12];
    __shared__ float  sZ[12], sH[32];
    __shared__ float4 sPix4[4];           // 16 final pixels

    const int t = threadIdx.x;            // 0..255

    // ---- per-(layer,qubit) 2x2 gates ----
    if (t < 36) {
        const float* wp = w + t * 3;
        int layer = t / 12;
        float hx = 0.5f * wp[0], hy = 0.5f * wp[1], hz = 0.5f * wp[2];
        float cx, sx, cy, sy, cz, sz;
        __sincosf(hx, &sx, &cx);
        __sincosf(hy, &sy, &cy);
        __sincosf(hz, &sz, &cz);
        float2 RX00 = make_float2(cx, 0.f), RX01 = make_float2(0.f, -sx);
        float2 RX10 = make_float2(0.f, -sx), RX11 = make_float2(cx, 0.f);
        float2 RY00 = make_float2(cy, 0.f), RY01 = make_float2(-sy, 0.f);
        float2 RY10 = make_float2(sy, 0.f), RY11 = make_float2(cy, 0.f);
        float2 t00 = cmul(RY00, RX00), t00b = cmul(RY01, RX10);
        float2 t01 = cmul(RY00, RX01), t01b = cmul(RY01, RX11);
        float2 t10 = cmul(RY10, RX00), t10b = cmul(RY11, RX10);
        float2 t11 = cmul(RY10, RX01), t11b = cmul(RY11, RX11);
        float2 A00 = make_float2(t00.x + t00b.x, t00.y + t00b.y);
        float2 A01 = make_float2(t01.x + t01b.x, t01.y + t01b.y);
        float2 A10 = make_float2(t10.x + t10b.x, t10.y + t10b.y);
        float2 A11 = make_float2(t11.x + t11b.x, t11.y + t11b.y);
        if (layer == 2) {
            // final RZ is diagonal phase -> probabilities unchanged; drop it
            sG[t][0] = A00; sG[t][1] = A01; sG[t][2] = A10; sG[t][3] = A11;
        } else {
            float2 RZ0 = make_float2(cz, -sz), RZ1 = make_float2(cz, sz);
            sG[t][0] = cmul(RZ0, A00);
            sG[t][1] = cmul(RZ0, A01);
            sG[t][2] = cmul(RZ1, A10);
            sG[t][3] = cmul(RZ1, A11);
        }
    }
    // ---- basis of inverse CNOT-ring permutation (GF(2)-linear) ----
    if (t >= 64 && t < 76) {
        int b = t - 64;
        int j = 1 << b;
        #pragma unroll
        for (int q = 11; q >= 0; q--) {
            int c = 11 - q;
            int tt = 11 - ((q + 1) % 12);
            if ((j >> c) & 1) j ^= (1 << tt);
        }
        sBinv[b] = j;
    }
    // ---- forward-perm parity masks ----
    if (t == 128) {
        int m[12];
        #pragma unroll
        for (int k = 0; k < 12; k++) m[k] = 1 << k;
        #pragma unroll
        for (int q = 0; q < 12; q++) {
            int c = 11 - q;
            int tt = 11 - ((q + 1) % 12);
            m[tt] ^= m[c];
        }
        #pragma unroll
        for (int k = 0; k < 12; k++) smask[k] = m[k];
    }
    __syncthreads();

    // ---- packed 4x4 stage matrices (layers 2,3) ----
    if (t < 192) {
        int s = t >> 4, e = t & 15;
        int l = 1 + s / 6, b = s % 6;
        int qlo = 11 - 2 * b, qhi = 10 - 2 * b;
        int eo = e >> 2, ei = e & 3;
        float2 mh = sG[l * 12 + qhi][(eo >> 1) * 2 + (ei >> 1)];
        float2 ml = sG[l * 12 + qlo][(eo & 1) * 2 + (ei & 1)];
        float2 mm = cmul(mh, ml);
        sM4[s][e] = make_float4(mm.x, mm.x, -mm.y, mm.y);
    }
    // ---- layer-1 product-state prefix tables ----
    if (t < 64) {                         // hi: qubits 0..5 <-> bits 11..6
        float2 p = make_float2(1.f, 0.f);
        #pragma unroll
        for (int q = 0; q < 6; q++) {
            int bit = (t >> (5 - q)) & 1;
            p = cmul(p, bit ? sG[q][2] : sG[q][0]);
        }
        sHi[t] = p;
    } else if (t < 128) {                 // lo: qubits 6..11 <-> bits 5..0
        int mI = t - 64;
        float2 p = make_float2(1.f, 0.f);
        #pragma unroll
        for (int q = 6; q < 12; q++) {
            int bit = (mI >> (11 - q)) & 1;
            p = cmul(p, bit ? sG[q][2] : sG[q][0]);
        }
        sLo[mI] = p;
    }
    __syncthreads();

    // gather-base for P^-1 over this thread's high bits (bits 4..11 = t)
    int gb = 0;
    #pragma unroll
    for (int b = 0; b < 8; b++)
        if ((t >> b) & 1) gb ^= sBinv[4 + b];
    const int B0 = sBinv[0], B1 = sBinv[1], B2 = sBinv[2], B3 = sBinv[3];

    u64 A[16];

    // ===== layer 2, round 0 (bits 0-3): P1-folded product gather =====
    #pragma unroll
    for (int k = 0; k < 16; k++) {
        int g = gb;
        if (k & 1) g ^= B0;
        if (k & 2) g ^= B1;
        if (k & 4) g ^= B2;
        if (k & 8) g ^= B3;
        float2 v = cmul(sHi[g >> 6], sLo[g & 63]);
        A[k] = pack2(v.x, v.y);
    }
    stage_pair(sM4[0], sM4[1], A);
    #pragma unroll
    for (int k = 0; k < 16; k++) buf[PHYS((t << 4) | k)] = A[k];
    __syncthreads();

    // ===== layer 2, round 1 (bits 4-7) =====
    {
        const int hi = t >> 4, lo = t & 15;
        #pragma unroll
        for (int k = 0; k < 16; k++) A[k] = buf[PHYS((hi << 8) | (k << 4) | lo)];
        stage_pair(sM4[2], sM4[3], A);
        #pragma unroll
        for (int k = 0; k < 16; k++) buf[PHYS((hi << 8) | (k << 4) | lo)] = A[k];
    }
    __syncthreads();

    // ===== layer 2, round 2 (bits 8-11) =====
    #pragma unroll
    for (int k = 0; k < 16; k++) A[k] = buf[PHYS((k << 8) | t)];
    stage_pair(sM4[4], sM4[5], A);
    #pragma unroll
    for (int k = 0; k < 16; k++) buf[PHYS((k << 8) | t)] = A[k];
    __syncthreads();

    // ===== layer 3, round 0 (bits 0-3): P2-folded gather =====
    #pragma unroll
    for (int k = 0; k < 16; k++) {
        int g = gb;
        if (k & 1) g ^= B0;
        if (k & 2) g ^= B1;
        if (k & 4) g ^= B2;
        if (k & 8) g ^= B3;
        A[k] = buf[PHYS(g)];
    }
    __syncthreads();                      // all permuted reads before overwrite
    stage_pair(sM4[6], sM4[7], A);
    #pragma unroll
    for (int k = 0; k < 16; k++) buf[PHYS((t << 4) | k)] = A[k];
    __syncthreads();

    // ===== layer 3, round 1 (bits 4-7) =====
    {
        const int hi = t >> 4, lo = t & 15;
        #pragma unroll
        for (int k = 0; k < 16; k++) A[k] = buf[PHYS((hi << 8) | (k << 4) | lo)];
        stage_pair(sM4[8], sM4[9], A);
        #pragma unroll
        for (int k = 0; k < 16; k++) buf[PHYS((hi << 8) | (k << 4) | lo)] = A[k];
    }
    __syncthreads();

    // ===== layer 3, round 2 (bits 8-11): reduce from registers =====
    #pragma unroll
    for (int k = 0; k < 16; k++) A[k] = buf[PHYS((k << 8) | t)];
    __syncthreads();                      // buf reads done (buf reused for WHT)
    stage_pair(sM4[10], sM4[11], A);

    // per-thread probabilities + 4-bit Walsh-Hadamard over k
    float pr[16];
    #pragma unroll
    for (int k = 0; k < 16; k++) {
        float2 v = unpack2(A[k]);
        pr[k] = fmaf(v.x, v.x, v.y * v.y);
    }
    #pragma unroll
    for (int s = 1; s < 16; s <<= 1) {
        #pragma unroll
        for (int k = 0; k < 16; k++) {
            if (!(k & s)) {
                float u = pr[k], vv = pr[k | s];
                pr[k] = u + vv;
                pr[k | s] = u - vv;
            }
        }
    }
    // spill WHT to private padded smem slice (dynamic index)
    float* Wb = reinterpret_cast<float*>(buf) + t * 17;
    #pragma unroll
    for (int h = 0; h < 16; h++) Wb[h] = pr[h];

    // zloc[q] = sign(t) * W[mask_hi]; sign from low 8 bits of mask (P3 fold)
    float zloc[12];
    #pragma unroll
    for (int q = 0; q < 12; q++) {
        int m = smask[11 - q];
        float wv = Wb[(m >> 8) & 15];
        zloc[q] = (__popc(t & m & 0xFF) & 1) ? -wv : wv;
    }
    #pragma unroll
    for (int q = 0; q < 12; q++) {
        float x = zloc[q];
        #pragma unroll
        for (int off = 16; off > 0; off >>= 1)
            x += __shfl_down_sync(0xFFFFFFFFu, x, off);
        zloc[q] = x;
    }
    int warp = t >> 5, lane = t & 31;
    if (lane == 0) {
        #pragma unroll
        for (int q = 0; q < 12; q++) sPart[warp][q] = zloc[q];
    }
    __syncthreads();
    if (t < 12) {
        float s = 0.f;
        #pragma unroll
        for (int wi = 0; wi < 8; wi++) s += sPart[wi][t];
        sZ[t] = s;
    }
    __syncthreads();

    // ---- MLP head: 12 -> 32 (ReLU) -> 16 (sigmoid) ----
    if (t < 32) {
        float acc = b1[t];
        #pragma unroll
        for (int k = 0; k < 12; k++) acc += W1[t * 12 + k] * sZ[k];
        sH[t] = fmaxf(acc, 0.f);
    }
    __syncthreads();
    if (t < 16) {
        float acc = b2[t];
        #pragma unroll
        for (int k = 0; k < 32; k++) acc += W2[t * 32 + k] * sH[k];
        reinterpret_cast<float*>(sPix4)[t] = 1.f / (1.f + __expf(-acc));
    }
    __syncthreads();

    // ===== broadcast: grid-strided slice, 8 front-batched STG.128 =====
    const int gt = blockIdx.x * 256 + t;
    const int stride = gridDim.x * 256;            // multiple of 4
    float4 v = sPix4[gt & 3];                      // constant per thread
    int i = gt;
    for (; i + 7 * stride < n4; i += 8 * stride) {
        out[i]              = v;
        out[i + stride]     = v;
        out[i + 2 * stride] = v;
        out[i + 3 * stride] = v;
        out[i + 4 * stride] = v;
        out[i + 5 * stride] = v;
        out[i + 6 * stride] = v;
        out[i + 7 * stride] = v;
    }
    for (; i < n4; i += stride) out[i] = v;
}

extern "C" void kernel_launch(void* const* d_in, const int* in_sizes, int n_in,
                              void* d_out, int out_size)
{
    // metadata order: images, qweights, W1, b1, W2, b2
    const float* w  = (const float*)d_in[1];
    const float* W1 = (const float*)d_in[2];
    const float* b1 = (const float*)d_in[3];
    const float* W2 = (const float*)d_in[4];
    const float* b2 = (const float*)d_in[5];

    int n4 = out_size / 4;                         // float4 count
    qae_fused_kernel<<<148, 256>>>(w, W1, b1, W2, b2, (float4*)d_out, n4);
}

// round 8
// speedup vs baseline: 1.0137x; 1.0137x over previous
#include <cuda_runtime.h>
#include <math.h>

typedef unsigned long long u64;

// padded phys layout: one 8B slot per 16 amps -> conflict-free in all 3 rounds
__device__ __forceinline__ int PHYS(int i) { return i + (i >> 4); }

// CNOT-ring permutation constants (circuit-structural, derived offline):
//   inverse-perm basis P^-1(1<<b):
//     BINV[0]=0xC01, BINV[b]=3<<(b-1) for b>=1
//   forward-perm parity masks: bit_b(P(j)) = parity(j & PMASK[b])
#define PM11 0x7FF
#define PM10 0xC00
#define PM9  0xE00
#define PM8  0xF00
#define PM7  0xF80
#define PM6  0xFC0
#define PM5  0xFE0
#define PM4  0xFF0
#define PM3  0xFF8
#define PM2  0xFFC
#define PM1  0xFFE
#define PM0  0xFFF

__device__ __forceinline__ float2 cmul(float2 a, float2 b) {
    return make_float2(a.x * b.x - a.y * b.y, a.x * b.y + a.y * b.x);
}
__device__ __forceinline__ u64 pack2(float x, float y) {
    u64 r; asm("mov.b64 %0, {%1, %2};" : "=l"(r) : "f"(x), "f"(y)); return r;
}
__device__ __forceinline__ float2 unpack2(u64 v) {
    float2 r; asm("mov.b64 {%0, %1}, %2;" : "=f"(r.x), "=f"(r.y) : "l"(v)); return r;
}
__device__ __forceinline__ u64 swp(u64 v) {
    float2 t = unpack2(v); return pack2(t.y, t.x);
}
__device__ __forceinline__ u64 ffma2(u64 a, u64 b, u64 c) {
    u64 d; asm("fma.rn.f32x2 %0, %1, %2, %3;" : "=l"(d) : "l"(a), "l"(b), "l"(c)); return d;
}
__device__ __forceinline__ u64 fmul2(u64 a, u64 b) {
    u64 d; asm("mul.rn.f32x2 %0, %1, %2;" : "=l"(d) : "l"(a), "l"(b)); return d;
}

// inverse-perm gather index for amp (t<<4)|k, t in 0..255, k in 0..15
__device__ __forceinline__ int GATHER(int t, int k) {
    int g = (t << 3) ^ (t << 4);                 // XOR of BINV[4..11] per t bits
    if (k & 1) g ^= 0xC01;                       // BINV[0]
    if (k & 2) g ^= 0x003;                       // BINV[1]
    if (k & 4) g ^= 0x006;                       // BINV[2]
    if (k & 8) g ^= 0x00C;                       // BINV[3]
    return g;
}

// Apply two 4x4 complex stages to 16 register amps.
__device__ __forceinline__ void stage_pair(const float4* __restrict__ MshA,
                                           const float4* __restrict__ MshB,
                                           u64* A) {
    {   // stage A: quads {A[4c+j]}
        u64 mr[16], mi[16];
        #pragma unroll
        for (int e = 0; e < 16; e++) {
            float4 q = MshA[e];
            mr[e] = pack2(q.x, q.y);
            mi[e] = pack2(q.z, q.w);
        }
        #pragma unroll
        for (int c = 0; c < 4; c++) {
            u64 x0 = A[4*c], x1 = A[4*c+1], x2 = A[4*c+2], x3 = A[4*c+3];
            u64 s0 = swp(x0), s1 = swp(x1), s2 = swp(x2), s3 = swp(x3);
            #pragma unroll
            for (int e = 0; e < 4; e++) {
                u64 o = fmul2(mr[e*4+0], x0);
                o = ffma2(mi[e*4+0], s0, o);
                o = ffma2(mr[e*4+1], x1, o); o = ffma2(mi[e*4+1], s1, o);
                o = ffma2(mr[e*4+2], x2, o); o = ffma2(mi[e*4+2], s2, o);
                o = ffma2(mr[e*4+3], x3, o); o = ffma2(mi[e*4+3], s3, o);
                A[4*c+e] = o;
            }
        }
    }
    {   // stage B: quads {A[4j+c]}
        u64 mr[16], mi[16];
        #pragma unroll
        for (int e = 0; e < 16; e++) {
            float4 q = MshB[e];
            mr[e] = pack2(q.x, q.y);
            mi[e] = pack2(q.z, q.w);
        }
        #pragma unroll
        for (int c = 0; c < 4; c++) {
            u64 x0 = A[c], x1 = A[4+c], x2 = A[8+c], x3 = A[12+c];
            u64 s0 = swp(x0), s1 = swp(x1), s2 = swp(x2), s3 = swp(x3);
            #pragma unroll
            for (int e = 0; e < 4; e++) {
                u64 o = fmul2(mr[e*4+0], x0);
                o = ffma2(mi[e*4+0], s0, o);
                o = ffma2(mr[e*4+1], x1, o); o = ffma2(mi[e*4+1], s1, o);
                o = ffma2(mr[e*4+2], x2, o); o = ffma2(mi[e*4+2], s2, o);
                o = ffma2(mr[e*4+3], x3, o); o = ffma2(mi[e*4+3], s3, o);
                A[4*e+c] = o;
            }
        }
    }
}

// Fused: every block (one per SM) redundantly runs the 12-qubit sim + MLP in
// its own smem, then broadcasts its grid-strided slice of the 64 MiB output.
__global__ __launch_bounds__(256, 1)
void qae_fused_kernel(const float* __restrict__ w,     // (3,12,3)
                      const float* __restrict__ W1,    // (32,12)
                      const float* __restrict__ b1,    // (32,)
                      const float* __restrict__ W2,    // (16,32)
                      const float* __restrict__ b2,    // (16,)
                      float4* __restrict__ out, int n4)
{
    __shared__ u64    buf[4352];          // 4096 amps padded (34 KB)
    __shared__ float4 sM4[12][16];        // packed {mx,mx,-my,my} stage mats
    __shared__ float2 sG[36][4];          // per (layer,qubit) fused gate
    __shared__ float2 sHi[64], sLo[64];   // layer-1 product prefix tables
    __shared__ float  sPart[8][12];
    __shared__ float  sZ[12], sH[32];
    __shared__ float4 sPix4[4];           // 16 final pixels
    __shared__ float  sW1[384], sB1[32], sW2[512], sB2[16];

    const int t = threadIdx.x;            // 0..255

    // ---- prefetch MLP weights into smem (latency hidden under prologue) ----
    if (t < 96)
        reinterpret_cast<float4*>(sW1)[t] = reinterpret_cast<const float4*>(W1)[t];
    else if (t < 128)
        sB1[t - 96] = b1[t - 96];
    else
        reinterpret_cast<float4*>(sW2)[t - 128] = reinterpret_cast<const float4*>(W2)[t - 128];
    if (t < 16) sB2[t] = b2[t];

    // ---- per-(layer,qubit) 2x2 gates ----
    if (t < 36) {
        const float* wp = w + t * 3;
        int layer = t / 12;
        float hx = 0.5f * wp[0], hy = 0.5f * wp[1], hz = 0.5f * wp[2];
        float cx, sx, cy, sy, cz, sz;
        __sincosf(hx, &sx, &cx);
        __sincosf(hy, &sy, &cy);
        __sincosf(hz, &sz, &cz);
        float2 RX00 = make_float2(cx, 0.f), RX01 = make_float2(0.f, -sx);
        float2 RX10 = make_float2(0.f, -sx), RX11 = make_float2(cx, 0.f);
        float2 RY00 = make_float2(cy, 0.f), RY01 = make_float2(-sy, 0.f);
        float2 RY10 = make_float2(sy, 0.f), RY11 = make_float2(cy, 0.f);
        float2 t00 = cmul(RY00, RX00), t00b = cmul(RY01, RX10);
        float2 t01 = cmul(RY00, RX01), t01b = cmul(RY01, RX11);
        float2 t10 = cmul(RY10, RX00), t10b = cmul(RY11, RX10);
        float2 t11 = cmul(RY10, RX01), t11b = cmul(RY11, RX11);
        float2 A00 = make_float2(t00.x + t00b.x, t00.y + t00b.y);
        float2 A01 = make_float2(t01.x + t01b.x, t01.y + t01b.y);
        float2 A10 = make_float2(t10.x + t10b.x, t10.y + t10b.y);
        float2 A11 = make_float2(t11.x + t11b.x, t11.y + t11b.y);
        if (layer == 2) {
            // final RZ is diagonal phase -> probabilities unchanged; drop it
            sG[t][0] = A00; sG[t][1] = A01; sG[t][2] = A10; sG[t][3] = A11;
        } else {
            float2 RZ0 = make_float2(cz, -sz), RZ1 = make_float2(cz, sz);
            sG[t][0] = cmul(RZ0, A00);
            sG[t][1] = cmul(RZ0, A01);
            sG[t][2] = cmul(RZ1, A10);
            sG[t][3] = cmul(RZ1, A11);
        }
    }
    __syncthreads();

    // ---- packed 4x4 stage matrices (layers 2,3) ----
    if (t < 192) {
        int s = t >> 4, e = t & 15;
        int l = 1 + s / 6, b = s % 6;
        int qlo = 11 - 2 * b, qhi = 10 - 2 * b;
        int eo = e >> 2, ei = e & 3;
        float2 mh = sG[l * 12 + qhi][(eo >> 1) * 2 + (ei >> 1)];
        float2 ml = sG[l * 12 + qlo][(eo & 1) * 2 + (ei & 1)];
        float2 mm = cmul(mh, ml);
        sM4[s][e] = make_float4(mm.x, mm.x, -mm.y, mm.y);
    }
    // ---- layer-1 product-state prefix tables ----
    if (t < 64) {                         // hi: qubits 0..5 <-> bits 11..6
        float2 p = make_float2(1.f, 0.f);
        #pragma unroll
        for (int q = 0; q < 6; q++) {
            int bit = (t >> (5 - q)) & 1;
            p = cmul(p, bit ? sG[q][2] : sG[q][0]);
        }
        sHi[t] = p;
    } else if (t < 128) {                 // lo: qubits 6..11 <-> bits 5..0
        int mI = t - 64;
        float2 p = make_float2(1.f, 0.f);
        #pragma unroll
        for (int q = 6; q < 12; q++) {
            int bit = (mI >> (11 - q)) & 1;
            p = cmul(p, bit ? sG[q][2] : sG[q][0]);
        }
        sLo[mI] = p;
    }
    __syncthreads();

    u64 A[16];

    // ===== layer 2, round 0 (bits 0-3): P1-folded product gather =====
    #pragma unroll
    for (int k = 0; k < 16; k++) {
        int g = GATHER(t, k);
        float2 v = cmul(sHi[g >> 6], sLo[g & 63]);
        A[k] = pack2(v.x, v.y);
    }
    stage_pair(sM4[0], sM4[1], A);
    #pragma unroll
    for (int k = 0; k < 16; k++) buf[PHYS((t << 4) | k)] = A[k];
    __syncthreads();

    // ===== layer 2, round 1 (bits 4-7) =====
    {
        const int hi = t >> 4, lo = t & 15;
        #pragma unroll
        for (int k = 0; k < 16; k++) A[k] = buf[PHYS((hi << 8) | (k << 4) | lo)];
        stage_pair(sM4[2], sM4[3], A);
        #pragma unroll
        for (int k = 0; k < 16; k++) buf[PHYS((hi << 8) | (k << 4) | lo)] = A[k];
    }
    __syncthreads();

    // ===== layer 2, round 2 (bits 8-11) =====
    #pragma unroll
    for (int k = 0; k < 16; k++) A[k] = buf[PHYS((k << 8) | t)];
    stage_pair(sM4[4], sM4[5], A);
    #pragma unroll
    for (int k = 0; k < 16; k++) buf[PHYS((k << 8) | t)] = A[k];
    __syncthreads();

    // ===== layer 3, round 0 (bits 0-3): P2-folded gather =====
    #pragma unroll
    for (int k = 0; k < 16; k++) A[k] = buf[PHYS(GATHER(t, k))];
    __syncthreads();                      // all permuted reads before overwrite
    stage_pair(sM4[6], sM4[7], A);
    #pragma unroll
    for (int k = 0; k < 16; k++) buf[PHYS((t << 4) | k)] = A[k];
    __syncthreads();

    // ===== layer 3, round 1 (bits 4-7) =====
    {
        const int hi = t >> 4, lo = t & 15;
        #pragma unroll
        for (int k = 0; k < 16; k++) A[k] = buf[PHYS((hi << 8) | (k << 4) | lo)];
        stage_pair(sM4[8], sM4[9], A);
        #pragma unroll
        for (int k = 0; k < 16; k++) buf[PHYS((hi << 8) | (k << 4) | lo)] = A[k];
    }
    __syncthreads();

    // ===== layer 3, round 2 (bits 8-11): reduce from registers =====
    #pragma unroll
    for (int k = 0; k < 16; k++) A[k] = buf[PHYS((k << 8) | t)];
    stage_pair(sM4[10], sM4[11], A);

    // per-thread probabilities + 4-bit Walsh-Hadamard over k (in registers)
    float pr[16];
    #pragma unroll
    for (int k = 0; k < 16; k++) {
        float2 v = unpack2(A[k]);
        pr[k] = fmaf(v.x, v.x, v.y * v.y);
    }
    #pragma unroll
    for (int s = 1; s < 16; s <<= 1) {
        #pragma unroll
        for (int k = 0; k < 16; k++) {
            if (!(k & s)) {
                float u = pr[k], vv = pr[k | s];
                pr[k] = u + vv;
                pr[k | s] = u - vv;
            }
        }
    }

    // <Z_q> with P3 folded: zloc[q] = sign(t) * WHT[mask_hi], all constexpr.
    // q -> PMASK[11-q]; hi nibble indexes pr[], low byte gives thread-sign.
    float zloc[12];
    {
        const int MQ[12] = {PM11, PM10, PM9, PM8, PM7, PM6,
                            PM5,  PM4,  PM3, PM2, PM1, PM0};
        #pragma unroll
        for (int q = 0; q < 12; q++) {
            const int m = MQ[q];
            float wv = pr[(m >> 8) & 15];          // constexpr index
            zloc[q] = (__popc(t & (m & 0xFF)) & 1) ? -wv : wv;
        }
    }
    #pragma unroll
    for (int q = 0; q < 12; q++) {
        float x = zloc[q];
        #pragma unroll
        for (int off = 16; off > 0; off >>= 1)
            x += __shfl_down_sync(0xFFFFFFFFu, x, off);
        zloc[q] = x;
    }
    int warp = t >> 5, lane = t & 31;
    if (lane == 0) {
        #pragma unroll
        for (int q = 0; q < 12; q++) sPart[warp][q] = zloc[q];
    }
    __syncthreads();
    if (t < 12) {
        float s = 0.f;
        #pragma unroll
        for (int wi = 0; wi < 8; wi++) s += sPart[wi][t];
        sZ[t] = s;
    }
    __syncthreads();

    // ---- MLP head: 12 -> 32 (ReLU) -> 16 (sigmoid), weights in smem ----
    if (t < 32) {
        float acc = sB1[t];
        #pragma unroll
        for (int k = 0; k < 12; k++) acc += sW1[t * 12 + k] * sZ[k];
        sH[t] = fmaxf(acc, 0.f);
    }
    __syncthreads();
    if (t < 16) {
        float acc = sB2[t];
        #pragma unroll
        for (int k = 0; k < 32; k++) acc += sW2[t * 32 + k] * sH[k];
        reinterpret_cast<float*>(sPix4)[t] = 1.f / (1.f + __expf(-acc));
    }
    __syncthreads();

    // ===== broadcast: grid-strided slice, 8 front-batched STG.128 =====
    const int gt = blockIdx.x * 256 + t;
    const int stride = gridDim.x * 256;            // multiple of 4
    float4 v = sPix4[gt & 3];                      // constant per thread
    int i = gt;
    for (; i + 7 * stride < n4; i += 8 * stride) {
        out[i]              = v;
        out[i + stride]     = v;
        out[i + 2 * stride] = v;
        out[i + 3 * stride] = v;
        out[i + 4 * stride] = v;
        out[i + 5 * stride] = v;
        out[i + 6 * stride] = v;
        out[i + 7 * stride] = v;
    }
    for (; i < n4; i += stride) out[i] = v;
}

extern "C" void kernel_launch(void* const* d_in, const int* in_sizes, int n_in,
                              void* d_out, int out_size)
{
    // metadata order: images, qweights, W1, b1, W2, b2
    const float* w  = (const float*)d_in[1];
    const float* W1 = (const float*)d_in[2];
    const float* b1 = (const float*)d_in[3];
    const float* W2 = (const float*)d_in[4];
    const float* b2 = (const float*)d_in[5];

    int n4 = out_size / 4;                         // float4 count
    qae_fused_kernel<<<148, 256>>>(w, W1, b1, W2, b2, (float4*)d_out, n4);
}